// round 3
// baseline (speedup 1.0000x reference)
#include <cuda_runtime.h>
#include <math.h>

// ---------------------------------------------------------------------------
// Problem dims
// ---------------------------------------------------------------------------
#define BB    16
#define CEMB  1024
#define TT    2048
#define KK    4096
#define CCB   64

// Output layout (float32, tuple order flattened)
// NOTE: OUT_XPROJ/OUT_QPROJ are == 2 (mod 4): only float2/scalar access allowed there.
#define OUT_CODES   ((size_t)0)
#define N_CODES     ((size_t)BB * TT)                       // 32768
#define OUT_QUANT   (OUT_CODES + N_CODES)
#define N_QUANT     ((size_t)BB * CEMB * TT)                // 33554432
#define OUT_CBLOSS  (OUT_QUANT + N_QUANT)
#define OUT_COMMIT  (OUT_CBLOSS + 1)
#define OUT_XPROJ   (OUT_COMMIT + 1)
#define N_XPROJ     ((size_t)BB * CCB * TT)                 // 2097152
#define OUT_QPROJ   (OUT_XPROJ + N_XPROJ)

#define LOSS_INV    (1.0f / 2097152.0f)                     // exact (2^-21)

// ---------------------------------------------------------------------------
// Device scratch (no allocations allowed) — 16B aligned for float4 paths
// ---------------------------------------------------------------------------
__device__ __align__(16) float g_Win[CCB * CEMB];    // (64, 1024)
__device__ __align__(16) float g_Wout[CEMB * CCB];   // (1024, 64)
__device__ __align__(16) float g_cbn[KK * CCB];      // normalized codebook (4096, 64)
__device__ __align__(16) float g_chalf[KK];          // 0.5 * ||cb_n||^2

// ---------------------------------------------------------------------------
// Prep: W_in = g * v / ||v_row||   (rows of length 1024)
// ---------------------------------------------------------------------------
__global__ void prep_win(const float* __restrict__ v, const float* __restrict__ g) {
    const int o = blockIdx.x;
    __shared__ float red[256];
    float s = 0.f;
    for (int i = threadIdx.x; i < CEMB; i += 256) {
        float a = v[o * CEMB + i];
        s += a * a;
    }
    red[threadIdx.x] = s;
    __syncthreads();
    for (int st = 128; st > 0; st >>= 1) {
        if (threadIdx.x < st) red[threadIdx.x] += red[threadIdx.x + st];
        __syncthreads();
    }
    const float scale = g[o] / sqrtf(red[0]);
    for (int i = threadIdx.x; i < CEMB; i += 256)
        g_Win[o * CEMB + i] = v[o * CEMB + i] * scale;
}

// W_out rows of length 64
__global__ void prep_wout(const float* __restrict__ v, const float* __restrict__ g) {
    const int o = blockIdx.x;
    const int t = threadIdx.x;
    const float a = v[o * CCB + t];
    __shared__ float red[64];
    red[t] = a * a;
    __syncthreads();
    for (int st = 32; st > 0; st >>= 1) {
        if (t < st) red[t] += red[t + st];
        __syncthreads();
    }
    g_Wout[o * CCB + t] = a * (g[o] / sqrtf(red[0]));
}

// cb_n = cb / max(||cb||, 1e-12); c_half = 0.5 * sum(cb_n^2); zero loss slots
__global__ void prep_cb(const float* __restrict__ cb, float* __restrict__ out) {
    const int k = blockIdx.x;
    const int t = threadIdx.x;
    const float a = cb[k * CCB + t];
    __shared__ float red[64];
    red[t] = a * a;
    __syncthreads();
    for (int st = 32; st > 0; st >>= 1) {
        if (t < st) red[t] += red[t + st];
        __syncthreads();
    }
    const float denom = fmaxf(sqrtf(red[0]), 1e-12f);
    const float e = a / denom;
    g_cbn[k * CCB + t] = e;
    __syncthreads();
    red[t] = e * e;
    __syncthreads();
    for (int st = 32; st > 0; st >>= 1) {
        if (t < st) red[t] += red[t + st];
        __syncthreads();
    }
    if (t == 0) g_chalf[k] = 0.5f * red[0];
    if (k == 0 && t == 0) {
        out[OUT_CBLOSS] = 0.f;
        out[OUT_COMMIT] = 0.f;
    }
}

// ---------------------------------------------------------------------------
// x_proj[b,o,t] = sum_i W_in[o,i] * x[b,i,t].  Tile: 64(o) x 128(t), K chunks 32.
// grid (T/128, B), block 256.  Each thread: 4o x 8t accumulators.
// ---------------------------------------------------------------------------
__global__ __launch_bounds__(256) void xproj_kernel(const float* __restrict__ x,
                                                    float* __restrict__ out) {
    const int b  = blockIdx.y;
    const int t0 = blockIdx.x * 128;
    __shared__ float sW[32][68];    // sW[i][o]
    __shared__ float sX[32][132];   // sX[i][t]
    const int tid = threadIdx.x;
    const int tx = tid & 15;        // t group (8 each)
    const int ty = tid >> 4;        // o group (4 each)

    float acc[4][8];
#pragma unroll
    for (int i = 0; i < 4; i++)
#pragma unroll
        for (int j = 0; j < 8; j++) acc[i][j] = 0.f;

    for (int i0 = 0; i0 < CEMB; i0 += 32) {
#pragma unroll
        for (int j = 0; j < 8; j++) {           // 64o x 32i = 2048 floats
            int idx = tid + j * 256;
            int ii = idx & 31, o = idx >> 5;
            sW[ii][o] = g_Win[o * CEMB + i0 + ii];
        }
#pragma unroll
        for (int j = 0; j < 4; j++) {           // 32i x 128t = 1024 float4
            int v = tid + j * 256;
            int i = v >> 5, t4 = (v & 31) << 2;
            float4 val = *(const float4*)&x[((size_t)b * CEMB + i0 + i) * TT + t0 + t4];
            *(float4*)&sX[i][t4] = val;
        }
        __syncthreads();
#pragma unroll
        for (int i = 0; i < 32; i++) {
            float4 wf = *(const float4*)&sW[i][ty * 4];
            float4 x0 = *(const float4*)&sX[i][tx * 8];
            float4 x1 = *(const float4*)&sX[i][tx * 8 + 4];
            float w[4] = {wf.x, wf.y, wf.z, wf.w};
            float xv[8] = {x0.x, x0.y, x0.z, x0.w, x1.x, x1.y, x1.z, x1.w};
#pragma unroll
            for (int oo = 0; oo < 4; oo++)
#pragma unroll
                for (int tt = 0; tt < 8; tt++)
                    acc[oo][tt] = fmaf(w[oo], xv[tt], acc[oo][tt]);
        }
        __syncthreads();
    }
    // Output region is only 8B-aligned (offset % 4 == 2) -> float2 stores.
#pragma unroll
    for (int oo = 0; oo < 4; oo++) {
        size_t base = OUT_XPROJ + ((size_t)b * CCB + ty * 4 + oo) * TT + t0 + tx * 8;
#pragma unroll
        for (int p = 0; p < 4; p++)
            *(float2*)&out[base + 2 * p] = make_float2(acc[oo][2 * p], acc[oo][2 * p + 1]);
    }
}

// ---------------------------------------------------------------------------
// Argmin/gather/loss kernel. One thread per (b,t). block 128, grid 256.
// score(k) = inv * dot(x_proj, cb_n[k]) - 0.5*||cb_n[k]||^2   (argmax == ref argmin)
// ---------------------------------------------------------------------------
__global__ __launch_bounds__(128) void argmin_kernel(float* __restrict__ out,
                                                     const float* __restrict__ cb_raw) {
    const int tid = threadIdx.x;
    const int g = blockIdx.x * 128 + tid;
    const int b = g >> 11;
    const int t = g & (TT - 1);

    __shared__ float s_cb[64 * 64];
    __shared__ float s_ch[64];
    __shared__ float s_red[128];

    // load x_proj column (unnormalized kept for loss) — strided scalar loads
    float xp[64];
    const size_t xbase = OUT_XPROJ + (size_t)b * CCB * TT + t;
#pragma unroll
    for (int c = 0; c < 64; c++) xp[c] = out[xbase + (size_t)c * TT];

    float ss = 0.f;
#pragma unroll
    for (int c = 0; c < 64; c++) ss = fmaf(xp[c], xp[c], ss);
    const float inv = 1.0f / fmaxf(sqrtf(ss), 1e-12f);

    float best = -1e30f;
    int bestk = 0;

    for (int kt = 0; kt < KK; kt += 64) {
#pragma unroll
        for (int j = 0; j < 8; j++) {               // 64*64 floats = 1024 float4
            int v = tid + j * 128;
            *(float4*)&s_cb[v * 4] = *(const float4*)&g_cbn[(size_t)kt * 64 + v * 4];
        }
        if (tid < 64) s_ch[tid] = g_chalf[kt + tid];
        __syncthreads();

#pragma unroll 4
        for (int kk = 0; kk < 64; kk++) {
            const float4* r = (const float4*)&s_cb[kk * 64];
            float d0 = 0.f, d1 = 0.f, d2 = 0.f, d3 = 0.f;
#pragma unroll
            for (int j = 0; j < 16; j++) {
                float4 v = r[j];
                d0 = fmaf(xp[4 * j + 0], v.x, d0);
                d1 = fmaf(xp[4 * j + 1], v.y, d1);
                d2 = fmaf(xp[4 * j + 2], v.z, d2);
                d3 = fmaf(xp[4 * j + 3], v.w, d3);
            }
            float score = ((d0 + d1) + (d2 + d3)) * inv - s_ch[kk];
            if (score > best) { best = score; bestk = kt + kk; }  // strict > == first-index ties
        }
        __syncthreads();
    }

    // codes (as float, exact for k < 2^24)
    out[OUT_CODES + g] = (float)bestk;

    // gather raw codebook row -> quantized_proj (strided scalar), accumulate loss
    float ls = 0.f;
    const float* q = cb_raw + (size_t)bestk * CCB;
    const size_t qbase = OUT_QPROJ + (size_t)b * CCB * TT + t;
#pragma unroll
    for (int c = 0; c < 64; c++) {
        float qv = q[c];
        out[qbase + (size_t)c * TT] = qv;
        float dd = xp[c] - qv;
        ls = fmaf(dd, dd, ls);
    }

    s_red[tid] = ls;
    __syncthreads();
    for (int st = 64; st > 0; st >>= 1) {
        if (tid < st) s_red[tid] += s_red[tid + st];
        __syncthreads();
    }
    if (tid == 0) {
        float v = s_red[0] * LOSS_INV;
        atomicAdd(&out[OUT_CBLOSS], v);
        atomicAdd(&out[OUT_COMMIT], v);
    }
}

// ---------------------------------------------------------------------------
// quantized[b,o,t] = sum_c W_out[o,c] * qproj[b,c,t].  K=64 single pass.
// Tile 64(o) x 64(t). grid (T/64, CEMB/64, B), block 256, each thread 4o x 4t.
// ---------------------------------------------------------------------------
__global__ __launch_bounds__(256) void wout_kernel(float* __restrict__ out) {
    const int b  = blockIdx.z;
    const int o0 = blockIdx.y * 64;
    const int t0 = blockIdx.x * 64;
    __shared__ float sW[64][68];   // sW[c][o]
    __shared__ float sQ[64][68];   // sQ[c][t]
    const int tid = threadIdx.x;
    const int tx = tid & 15;       // t group (4)
    const int ty = tid >> 4;       // o group (4)

#pragma unroll
    for (int j = 0; j < 16; j++) {        // 64o x 64c
        int idx = tid + j * 256;
        int c = idx & 63, o = idx >> 6;
        sW[c][o] = g_Wout[(size_t)(o0 + o) * CCB + c];
    }
    // q_proj region is only 8B-aligned (offset % 4 == 2) -> float2 loads.
#pragma unroll
    for (int j = 0; j < 4; j++) {         // 64c x 64t, 4 floats per thread per j
        int v = tid + j * 256;
        int c = v >> 4, t4 = (v & 15) << 2;
        size_t src = OUT_QPROJ + ((size_t)b * CCB + c) * TT + t0 + t4;
        float2 a0 = *(const float2*)&out[src];
        float2 a1 = *(const float2*)&out[src + 2];
        sQ[c][t4 + 0] = a0.x; sQ[c][t4 + 1] = a0.y;
        sQ[c][t4 + 2] = a1.x; sQ[c][t4 + 3] = a1.y;
    }
    __syncthreads();

    float acc[4][4];
#pragma unroll
    for (int i = 0; i < 4; i++)
#pragma unroll
        for (int j = 0; j < 4; j++) acc[i][j] = 0.f;

#pragma unroll
    for (int c = 0; c < 64; c++) {
        float4 wf = *(const float4*)&sW[c][ty * 4];
        float4 qf = *(const float4*)&sQ[c][tx * 4];
        float w[4] = {wf.x, wf.y, wf.z, wf.w};
        float qv[4] = {qf.x, qf.y, qf.z, qf.w};
#pragma unroll
        for (int oo = 0; oo < 4; oo++)
#pragma unroll
            for (int tt = 0; tt < 4; tt++)
                acc[oo][tt] = fmaf(w[oo], qv[tt], acc[oo][tt]);
    }
    // OUT_QUANT region offset % 4 == 0 -> float4 stores are legal.
#pragma unroll
    for (int oo = 0; oo < 4; oo++) {
        size_t base = OUT_QUANT + ((size_t)b * CEMB + o0 + ty * 4 + oo) * TT + t0 + tx * 4;
        *(float4*)&out[base] = make_float4(acc[oo][0], acc[oo][1], acc[oo][2], acc[oo][3]);
    }
}

// ---------------------------------------------------------------------------
extern "C" void kernel_launch(void* const* d_in, const int* in_sizes, int n_in,
                              void* d_out, int out_size) {
    const float* x     = (const float*)d_in[0];
    const float* v_in  = (const float*)d_in[1];
    const float* g_in  = (const float*)d_in[2];
    const float* v_out = (const float*)d_in[3];
    const float* g_out = (const float*)d_in[4];
    const float* cb    = (const float*)d_in[5];
    float* out = (float*)d_out;

    prep_win<<<CCB, 256>>>(v_in, g_in);
    prep_wout<<<CEMB, 64>>>(v_out, g_out);
    prep_cb<<<KK, 64>>>(cb, out);
    xproj_kernel<<<dim3(TT / 128, BB), 256>>>(x, out);
    argmin_kernel<<<BB * TT / 128, 128>>>(out, cb);
    wout_kernel<<<dim3(TT / 64, CEMB / 64, BB), 256>>>(out);
}

// round 8
// speedup vs baseline: 2.0706x; 2.0706x over previous
#include <cuda_runtime.h>
#include <cuda_fp16.h>
#include <math.h>
#include <stdint.h>

// ---------------------------------------------------------------------------
// Problem dims
// ---------------------------------------------------------------------------
#define BB    16
#define CEMB  1024
#define TT    2048
#define KK    4096
#define CCB   64

// Output layout (float32, tuple order flattened)
// NOTE: OUT_XPROJ/OUT_QPROJ are == 2 (mod 4): only float2/scalar access there.
#define OUT_CODES   ((size_t)0)
#define N_CODES     ((size_t)BB * TT)                       // 32768
#define OUT_QUANT   (OUT_CODES + N_CODES)
#define N_QUANT     ((size_t)BB * CEMB * TT)                // 33554432
#define OUT_CBLOSS  (OUT_QUANT + N_QUANT)
#define OUT_COMMIT  (OUT_CBLOSS + 1)
#define OUT_XPROJ   (OUT_COMMIT + 1)
#define N_XPROJ     ((size_t)BB * CCB * TT)                 // 2097152
#define OUT_QPROJ   (OUT_XPROJ + N_XPROJ)

#define LOSS_INV    (1.0f / 2097152.0f)                     // exact (2^-21)

// ---------------------------------------------------------------------------
// Device scratch (no allocations allowed)
// ---------------------------------------------------------------------------
__device__ __align__(16) float  g_Win[CCB * CEMB];    // (64, 1024)
__device__ __align__(16) float  g_Wout[CEMB * CCB];   // (1024, 64)
__device__ __align__(16) __half g_cbs[KK * 128];      // per code: [ch(64) | cl(64)]
__device__ __align__(16) float  g_chalf[KK];          // 0.5 * ||cb_n||^2

// ---------------------------------------------------------------------------
// PTX helpers (sm_80-compatible only — NO tcgen05 / NO 'a'-suffix features)
// ---------------------------------------------------------------------------
__device__ __forceinline__ uint32_t smem_u32(const void* p) {
    uint32_t a;
    asm("{ .reg .u64 t; cvta.to.shared.u64 t, %1; cvt.u32.u64 %0, t; }" : "=r"(a) : "l"(p));
    return a;
}
__device__ __forceinline__ void cpasync16(uint32_t dst, const void* src) {
    asm volatile("cp.async.cg.shared.global [%0], [%1], 16;" :: "r"(dst), "l"(src));
}
#define CP_COMMIT()  asm volatile("cp.async.commit_group;" ::: "memory")
#define CP_WAIT(n)   asm volatile("cp.async.wait_group %0;" :: "n"(n) : "memory")

__device__ __forceinline__ void ldsm_x4(uint32_t* r, uint32_t addr) {
    asm volatile("ldmatrix.sync.aligned.m8n8.x4.shared.b16 {%0,%1,%2,%3}, [%4];"
                 : "=r"(r[0]), "=r"(r[1]), "=r"(r[2]), "=r"(r[3]) : "r"(addr));
}
__device__ __forceinline__ void ldsm_x2(uint32_t* r, uint32_t addr) {
    asm volatile("ldmatrix.sync.aligned.m8n8.x2.shared.b16 {%0,%1}, [%2];"
                 : "=r"(r[0]), "=r"(r[1]) : "r"(addr));
}
__device__ __forceinline__ void mma16816(float* c, const uint32_t* a, const uint32_t* b) {
    asm volatile(
        "mma.sync.aligned.m16n8k16.row.col.f32.f16.f16.f32 "
        "{%0,%1,%2,%3}, {%4,%5,%6,%7}, {%8,%9}, {%0,%1,%2,%3};"
        : "+f"(c[0]), "+f"(c[1]), "+f"(c[2]), "+f"(c[3])
        : "r"(a[0]), "r"(a[1]), "r"(a[2]), "r"(a[3]), "r"(b[0]), "r"(b[1]));
}

// ---------------------------------------------------------------------------
// Prep kernels
// ---------------------------------------------------------------------------
__global__ void prep_win(const float* __restrict__ v, const float* __restrict__ g) {
    const int o = blockIdx.x;
    __shared__ float red[256];
    float s = 0.f;
    for (int i = threadIdx.x; i < CEMB; i += 256) {
        float a = v[o * CEMB + i];
        s += a * a;
    }
    red[threadIdx.x] = s;
    __syncthreads();
    for (int st = 128; st > 0; st >>= 1) {
        if (threadIdx.x < st) red[threadIdx.x] += red[threadIdx.x + st];
        __syncthreads();
    }
    const float scale = g[o] / sqrtf(red[0]);
    for (int i = threadIdx.x; i < CEMB; i += 256)
        g_Win[o * CEMB + i] = v[o * CEMB + i] * scale;
}

__global__ void prep_wout(const float* __restrict__ v, const float* __restrict__ g) {
    const int o = blockIdx.x;
    const int t = threadIdx.x;
    const float a = v[o * CCB + t];
    __shared__ float red[64];
    red[t] = a * a;
    __syncthreads();
    for (int st = 32; st > 0; st >>= 1) {
        if (t < st) red[t] += red[t + st];
        __syncthreads();
    }
    g_Wout[o * CCB + t] = a * (g[o] / sqrtf(red[0]));
}

// cb_n = cb / max(||cb||,1e-12); fp16 split [ch|cl]; c_half = 0.5*||cb_n||^2
__global__ void prep_cb(const float* __restrict__ cb, float* __restrict__ out) {
    const int k = blockIdx.x;
    const int t = threadIdx.x;
    const float a = cb[k * CCB + t];
    __shared__ float red[64];
    red[t] = a * a;
    __syncthreads();
    for (int st = 32; st > 0; st >>= 1) {
        if (t < st) red[t] += red[t + st];
        __syncthreads();
    }
    const float denom = fmaxf(sqrtf(red[0]), 1e-12f);
    const float e = a / denom;
    __half h = __float2half_rn(e);
    g_cbs[k * 128 + t]      = h;
    g_cbs[k * 128 + 64 + t] = __float2half_rn(e - __half2float(h));
    __syncthreads();
    red[t] = e * e;
    __syncthreads();
    for (int st = 32; st > 0; st >>= 1) {
        if (t < st) red[t] += red[t + st];
        __syncthreads();
    }
    if (t == 0) g_chalf[k] = 0.5f * red[0];
    if (k == 0 && t == 0) {
        out[OUT_CBLOSS] = 0.f;
        out[OUT_COMMIT] = 0.f;
    }
}

// ---------------------------------------------------------------------------
// x_proj GEMM (fp32 scalar — unchanged this round)
// ---------------------------------------------------------------------------
__global__ __launch_bounds__(256) void xproj_kernel(const float* __restrict__ x,
                                                    float* __restrict__ out) {
    const int b  = blockIdx.y;
    const int t0 = blockIdx.x * 128;
    __shared__ float sW[32][68];
    __shared__ float sX[32][132];
    const int tid = threadIdx.x;
    const int tx = tid & 15;
    const int ty = tid >> 4;

    float acc[4][8];
#pragma unroll
    for (int i = 0; i < 4; i++)
#pragma unroll
        for (int j = 0; j < 8; j++) acc[i][j] = 0.f;

    for (int i0 = 0; i0 < CEMB; i0 += 32) {
#pragma unroll
        for (int j = 0; j < 8; j++) {
            int idx = tid + j * 256;
            int ii = idx & 31, o = idx >> 5;
            sW[ii][o] = g_Win[o * CEMB + i0 + ii];
        }
#pragma unroll
        for (int j = 0; j < 4; j++) {
            int v = tid + j * 256;
            int i = v >> 5, t4 = (v & 31) << 2;
            float4 val = *(const float4*)&x[((size_t)b * CEMB + i0 + i) * TT + t0 + t4];
            *(float4*)&sX[i][t4] = val;
        }
        __syncthreads();
#pragma unroll
        for (int i = 0; i < 32; i++) {
            float4 wf = *(const float4*)&sW[i][ty * 4];
            float4 x0 = *(const float4*)&sX[i][tx * 8];
            float4 x1 = *(const float4*)&sX[i][tx * 8 + 4];
            float w[4] = {wf.x, wf.y, wf.z, wf.w};
            float xv[8] = {x0.x, x0.y, x0.z, x0.w, x1.x, x1.y, x1.z, x1.w};
#pragma unroll
            for (int oo = 0; oo < 4; oo++)
#pragma unroll
                for (int tt = 0; tt < 8; tt++)
                    acc[oo][tt] = fmaf(w[oo], xv[tt], acc[oo][tt]);
        }
        __syncthreads();
    }
#pragma unroll
    for (int oo = 0; oo < 4; oo++) {
        size_t base = OUT_XPROJ + ((size_t)b * CCB + ty * 4 + oo) * TT + t0 + tx * 8;
#pragma unroll
        for (int p = 0; p < 4; p++)
            *(float2*)&out[base + 2 * p] = make_float2(acc[oo][2 * p], acc[oo][2 * p + 1]);
    }
}

// ---------------------------------------------------------------------------
// Tensor-core argmin via mma.sync (m16n8k16 fp16 -> fp32), 3-term split.
// Per CTA: 128 tokens vs 4096 codes. 4 warps, warp w owns tokens w*32..+31.
// score = dot(xp, cb_n)*inv - 0.5||cb_n||^2 ; running argmax == ref argmin.
// ---------------------------------------------------------------------------
#define NCH       128                          // codes per chunk
#define NCHUNKS   (KK / NCH)                   // 32
#define SM_INV    0                            // 512 B  (float inv[128])
#define SM_BESTK  512                          // 512 B  (int bestk[128])
#define SM_CHALF  1024                         // 16 KB  (float chalf[4096])
#define SM_A      17408                        // 32 KB  (128 tokens x 256B [xh|xl])
#define SM_B0     50176                        // 32 KB
#define SM_B1     82944                        // 32 KB
#define SM_TOTAL  115712
#define SM_B(p)   ((p) ? SM_B1 : SM_B0)

__global__ __launch_bounds__(128, 1) void argmin_mma(float* __restrict__ out,
                                                     const float* __restrict__ cb_raw) {
    extern __shared__ __align__(256) char smem[];
    const uint32_t smb = smem_u32(smem);
    const int tid  = threadIdx.x;
    const int wid  = tid >> 5;
    const int lane = tid & 31;
    const int g7   = lane >> 2;     // C-fragment row group
    const int tg   = lane & 3;      // C-fragment col group

    const int token = blockIdx.x * 128 + tid;
    const int b = token >> 11;
    const int t = token & (TT - 1);

    // ---- kick off chalf + chunk0 prefetch (group 0) ----
    {
#pragma unroll
        for (int i = tid; i < 1024; i += 128)                       // 16 KB chalf
            cpasync16(smb + SM_CHALF + i * 16, (const char*)g_chalf + i * 16);
#pragma unroll
        for (int i = tid; i < 2048; i += 128) {                     // 32 KB chunk0
            int r = i >> 4, s = i & 15;
            cpasync16(smb + SM_B0 + r * 256 + ((s ^ (r & 7)) * 16),
                      (const char*)g_cbs + i * 16);
        }
        CP_COMMIT();
    }

    // ---- load x_proj column, inv, build swizzled A panel [xh|xl] ----
    {
        float xp[64];
        const size_t xbase = OUT_XPROJ + (size_t)b * CCB * TT + t;
#pragma unroll
        for (int c = 0; c < 64; c++) xp[c] = out[xbase + (size_t)c * TT];
        float ss = 0.f;
#pragma unroll
        for (int c = 0; c < 64; c++) ss = fmaf(xp[c], xp[c], ss);
        ((float*)(smem + SM_INV))[tid] = 1.0f / fmaxf(sqrtf(ss), 1e-12f);

#pragma unroll
        for (int s = 0; s < 8; s++) {
            uint32_t hw[4], lw[4];
#pragma unroll
            for (int j = 0; j < 4; j++) {
                float v0 = xp[8 * s + 2 * j], v1 = xp[8 * s + 2 * j + 1];
                __half h0 = __float2half_rn(v0), h1 = __float2half_rn(v1);
                __half l0 = __float2half_rn(v0 - __half2float(h0));
                __half l1 = __float2half_rn(v1 - __half2float(h1));
                hw[j] = (uint32_t)__half_as_ushort(h0) | ((uint32_t)__half_as_ushort(h1) << 16);
                lw[j] = (uint32_t)__half_as_ushort(l0) | ((uint32_t)__half_as_ushort(l1) << 16);
            }
            uint32_t off = (uint32_t)tid * 256 + ((s ^ (tid & 7)) * 16);
            *(uint4*)(smem + SM_A + off)       = make_uint4(hw[0], hw[1], hw[2], hw[3]);
            *(uint4*)(smem + SM_A + off + 128) = make_uint4(lw[0], lw[1], lw[2], lw[3]);
        }
    }
    __syncthreads();

    // ---- load resident A fragments (2 m-tiles x 4 k-tiles, hi & lo) ----
    uint32_t ah[2][4][4], al[2][4][4];
#pragma unroll
    for (int mt = 0; mt < 2; mt++) {
        const uint32_t rowb = smb + SM_A + (uint32_t)(wid * 32 + mt * 16 + (lane & 15)) * 256;
        const uint32_t r7 = (lane & 7);
        const uint32_t a4 = (lane >> 4);
#pragma unroll
        for (int kt = 0; kt < 4; kt++) {
            ldsm_x4(ah[mt][kt], rowb + (((2 * kt + a4) ^ r7) * 16));
            ldsm_x4(al[mt][kt], rowb + (((8 + 2 * kt + a4) ^ r7) * 16));
        }
    }

    // per-lane B ldmatrix offsets (8 k-tiles: ch0-3, cl0-3)
    uint32_t obch[4], obcl[4];
    {
        const uint32_t r7 = (lane & 7);
        const uint32_t a2 = (lane >> 3) & 1;
#pragma unroll
        for (int kt = 0; kt < 4; kt++) {
            obch[kt] = r7 * 256 + (((2 * kt + a2) ^ r7) * 16);
            obcl[kt] = r7 * 256 + (((8 + 2 * kt + a2) ^ r7) * 16);
        }
    }

    // per-lane token inverses
    float invr[4];
    {
        const float* si = (const float*)(smem + SM_INV);
#pragma unroll
        for (int r = 0; r < 4; r++) invr[r] = si[wid * 32 + r * 8 + g7];
    }

    float bestv[4] = {-1e30f, -1e30f, -1e30f, -1e30f};
    int   bestk[4] = {0, 0, 0, 0};
    const float* chs = (const float*)(smem + SM_CHALF);

    for (int c = 0; c < NCHUNKS; c++) {
        const int p = c & 1;
        if (c < NCHUNKS - 1) {
            const int pn = (c + 1) & 1;
            const char* src = (const char*)g_cbs + (size_t)(c + 1) * NCH * 256;
#pragma unroll
            for (int i = tid; i < 2048; i += 128) {
                int r = i >> 4, s = i & 15;
                cpasync16(smb + SM_B(pn) + r * 256 + ((s ^ (r & 7)) * 16), src + i * 16);
            }
            CP_COMMIT();
            CP_WAIT(1);
        } else {
            CP_WAIT(0);
        }
        __syncthreads();

        const uint32_t bbase = smb + SM_B(p);
        const int kchunk = c * NCH;

#pragma unroll 2
        for (int nt = 0; nt < NCH / 8; nt++) {
            const uint32_t nb = bbase + (uint32_t)nt * 8 * 256;
            uint32_t bch[4][2], bcl[4][2];
#pragma unroll
            for (int kt = 0; kt < 4; kt++) ldsm_x2(bch[kt], nb + obch[kt]);
#pragma unroll
            for (int kt = 0; kt < 4; kt++) ldsm_x2(bcl[kt], nb + obcl[kt]);

            float acc[8];
#pragma unroll
            for (int i = 0; i < 8; i++) acc[i] = 0.f;
#pragma unroll
            for (int mt = 0; mt < 2; mt++) {
#pragma unroll
                for (int kt = 0; kt < 4; kt++) mma16816(acc + 4 * mt, ah[mt][kt], bch[kt]);
#pragma unroll
                for (int kt = 0; kt < 4; kt++) mma16816(acc + 4 * mt, al[mt][kt], bch[kt]);
#pragma unroll
                for (int kt = 0; kt < 4; kt++) mma16816(acc + 4 * mt, ah[mt][kt], bcl[kt]);
            }

            const int col0 = kchunk + nt * 8 + 2 * tg;
            const float2 chv = *(const float2*)&chs[kchunk + nt * 8 + 2 * tg];
            float s;
            s = fmaf(acc[0], invr[0], -chv.x); if (s > bestv[0]) { bestv[0] = s; bestk[0] = col0; }
            s = fmaf(acc[1], invr[0], -chv.y); if (s > bestv[0]) { bestv[0] = s; bestk[0] = col0 + 1; }
            s = fmaf(acc[2], invr[1], -chv.x); if (s > bestv[1]) { bestv[1] = s; bestk[1] = col0; }
            s = fmaf(acc[3], invr[1], -chv.y); if (s > bestv[1]) { bestv[1] = s; bestk[1] = col0 + 1; }
            s = fmaf(acc[4], invr[2], -chv.x); if (s > bestv[2]) { bestv[2] = s; bestk[2] = col0; }
            s = fmaf(acc[5], invr[2], -chv.y); if (s > bestv[2]) { bestv[2] = s; bestk[2] = col0 + 1; }
            s = fmaf(acc[6], invr[3], -chv.x); if (s > bestv[3]) { bestv[3] = s; bestk[3] = col0; }
            s = fmaf(acc[7], invr[3], -chv.y); if (s > bestv[3]) { bestv[3] = s; bestk[3] = col0 + 1; }
        }
        __syncthreads();
    }

    // ---- combine across the 4 lanes of each quad (tie -> smaller k) ----
#pragma unroll
    for (int r = 0; r < 4; r++) {
#pragma unroll
        for (int off = 1; off < 4; off <<= 1) {
            float ov = __shfl_xor_sync(0xffffffffu, bestv[r], off);
            int   ok = __shfl_xor_sync(0xffffffffu, bestk[r], off);
            if (ov > bestv[r] || (ov == bestv[r] && ok < bestk[r])) {
                bestv[r] = ov; bestk[r] = ok;
            }
        }
    }
    if (tg == 0) {
        int* sbk = (int*)(smem + SM_BESTK);
#pragma unroll
        for (int r = 0; r < 4; r++) sbk[wid * 32 + r * 8 + g7] = bestk[r];
    }
    __syncthreads();

    // ---- tail: codes, gather q_proj, losses ----
    const int bk = ((const int*)(smem + SM_BESTK))[tid];
    out[OUT_CODES + token] = (float)bk;

    float xp[64];
    const size_t xbase = OUT_XPROJ + (size_t)b * CCB * TT + t;
#pragma unroll
    for (int c = 0; c < 64; c++) xp[c] = out[xbase + (size_t)c * TT];

    float ls = 0.f;
    const float* q = cb_raw + (size_t)bk * CCB;
    const size_t qbase = OUT_QPROJ + (size_t)b * CCB * TT + t;
#pragma unroll
    for (int c = 0; c < 64; c++) {
        float qv = q[c];
        out[qbase + (size_t)c * TT] = qv;
        float dd = xp[c] - qv;
        ls = fmaf(dd, dd, ls);
    }

    float* red = (float*)(smem + SM_INV);     // inv no longer needed
    red[tid] = ls;
    __syncthreads();
    for (int st = 64; st > 0; st >>= 1) {
        if (tid < st) red[tid] += red[tid + st];
        __syncthreads();
    }
    if (tid == 0) {
        float v = red[0] * LOSS_INV;
        atomicAdd(&out[OUT_CBLOSS], v);
        atomicAdd(&out[OUT_COMMIT], v);
    }
}

// ---------------------------------------------------------------------------
// W_out GEMM (fp32 scalar — unchanged this round)
// ---------------------------------------------------------------------------
__global__ __launch_bounds__(256) void wout_kernel(float* __restrict__ out) {
    const int b  = blockIdx.z;
    const int o0 = blockIdx.y * 64;
    const int t0 = blockIdx.x * 64;
    __shared__ float sW[64][68];
    __shared__ float sQ[64][68];
    const int tid = threadIdx.x;
    const int tx = tid & 15;
    const int ty = tid >> 4;

#pragma unroll
    for (int j = 0; j < 16; j++) {
        int idx = tid + j * 256;
        int c = idx & 63, o = idx >> 6;
        sW[c][o] = g_Wout[(size_t)(o0 + o) * CCB + c];
    }
#pragma unroll
    for (int j = 0; j < 4; j++) {
        int v = tid + j * 256;
        int c = v >> 4, t4 = (v & 15) << 2;
        size_t src = OUT_QPROJ + ((size_t)b * CCB + c) * TT + t0 + t4;
        float2 a0 = *(const float2*)&out[src];
        float2 a1 = *(const float2*)&out[src + 2];
        sQ[c][t4 + 0] = a0.x; sQ[c][t4 + 1] = a0.y;
        sQ[c][t4 + 2] = a1.x; sQ[c][t4 + 3] = a1.y;
    }
    __syncthreads();

    float acc[4][4];
#pragma unroll
    for (int i = 0; i < 4; i++)
#pragma unroll
        for (int j = 0; j < 4; j++) acc[i][j] = 0.f;

#pragma unroll
    for (int c = 0; c < 64; c++) {
        float4 wf = *(const float4*)&sW[c][ty * 4];
        float4 qf = *(const float4*)&sQ[c][tx * 4];
        float w[4] = {wf.x, wf.y, wf.z, wf.w};
        float qv[4] = {qf.x, qf.y, qf.z, qf.w};
#pragma unroll
        for (int oo = 0; oo < 4; oo++)
#pragma unroll
            for (int tt = 0; tt < 4; tt++)
                acc[oo][tt] = fmaf(w[oo], qv[tt], acc[oo][tt]);
    }
#pragma unroll
    for (int oo = 0; oo < 4; oo++) {
        size_t base = OUT_QUANT + ((size_t)b * CEMB + o0 + ty * 4 + oo) * TT + t0 + tx * 4;
        *(float4*)&out[base] = make_float4(acc[oo][0], acc[oo][1], acc[oo][2], acc[oo][3]);
    }
}

// ---------------------------------------------------------------------------
extern "C" void kernel_launch(void* const* d_in, const int* in_sizes, int n_in,
                              void* d_out, int out_size) {
    const float* x     = (const float*)d_in[0];
    const float* v_in  = (const float*)d_in[1];
    const float* g_in  = (const float*)d_in[2];
    const float* v_out = (const float*)d_in[3];
    const float* g_out = (const float*)d_in[4];
    const float* cb    = (const float*)d_in[5];
    float* out = (float*)d_out;

    cudaFuncSetAttribute(argmin_mma, cudaFuncAttributeMaxDynamicSharedMemorySize, SM_TOTAL);

    prep_win<<<CCB, 256>>>(v_in, g_in);
    prep_wout<<<CEMB, 64>>>(v_out, g_out);
    prep_cb<<<KK, 64>>>(cb, out);
    xproj_kernel<<<dim3(TT / 128, BB), 256>>>(x, out);
    argmin_mma<<<BB * TT / 128, 128, SM_TOTAL>>>(out, cb);
    wout_kernel<<<dim3(TT / 64, CEMB / 64, BB), 256>>>(out);
}

// round 13
// speedup vs baseline: 2.6406x; 1.2753x over previous
#include <cuda_runtime.h>
#include <cuda_fp16.h>
#include <math.h>
#include <stdint.h>

// ---------------------------------------------------------------------------
// Problem dims
// ---------------------------------------------------------------------------
#define BB    16
#define CEMB  1024
#define TT    2048
#define KK    4096
#define CCB   64

// Output layout (float32, tuple order flattened)
// NOTE: OUT_XPROJ/OUT_QPROJ are == 2 (mod 4): only float2/scalar access there.
#define OUT_CODES   ((size_t)0)
#define N_CODES     ((size_t)BB * TT)                       // 32768
#define OUT_QUANT   (OUT_CODES + N_CODES)
#define N_QUANT     ((size_t)BB * CEMB * TT)                // 33554432
#define OUT_CBLOSS  (OUT_QUANT + N_QUANT)
#define OUT_COMMIT  (OUT_CBLOSS + 1)
#define OUT_XPROJ   (OUT_COMMIT + 1)
#define N_XPROJ     ((size_t)BB * CCB * TT)                 // 2097152
#define OUT_QPROJ   (OUT_XPROJ + N_XPROJ)

#define LOSS_INV    (1.0f / 2097152.0f)                     // exact (2^-21)

// ---------------------------------------------------------------------------
// Device scratch (no allocations allowed)
// ---------------------------------------------------------------------------
__device__ __align__(16) __half g_Winh[CCB * CEMB];   // fp16 hi of W_in [o][k]
__device__ __align__(16) __half g_Winl[CCB * CEMB];   // fp16 lo residual
__device__ __align__(16) float  g_Wout[CEMB * CCB];   // (1024, 64)
__device__ __align__(16) __half g_cbs[KK * 128];      // per code: [ch(64) | cl(64)]
__device__ __align__(16) float  g_chalf[KK];          // 0.5 * ||cb_n||^2

// ---------------------------------------------------------------------------
// PTX helpers (sm_80-compatible only — NO tcgen05 / NO 'a'-suffix features)
// ---------------------------------------------------------------------------
__device__ __forceinline__ uint32_t smem_u32(const void* p) {
    uint32_t a;
    asm("{ .reg .u64 t; cvta.to.shared.u64 t, %1; cvt.u32.u64 %0, t; }" : "=r"(a) : "l"(p));
    return a;
}
__device__ __forceinline__ void cpasync16(uint32_t dst, const void* src) {
    asm volatile("cp.async.cg.shared.global [%0], [%1], 16;" :: "r"(dst), "l"(src));
}
#define CP_COMMIT()  asm volatile("cp.async.commit_group;" ::: "memory")
#define CP_WAIT(n)   asm volatile("cp.async.wait_group %0;" :: "n"(n) : "memory")

__device__ __forceinline__ void ldsm_x4(uint32_t* r, uint32_t addr) {
    asm volatile("ldmatrix.sync.aligned.m8n8.x4.shared.b16 {%0,%1,%2,%3}, [%4];"
                 : "=r"(r[0]), "=r"(r[1]), "=r"(r[2]), "=r"(r[3]) : "r"(addr));
}
__device__ __forceinline__ void ldsm_x4_t(uint32_t* r, uint32_t addr) {
    asm volatile("ldmatrix.sync.aligned.m8n8.x4.trans.shared.b16 {%0,%1,%2,%3}, [%4];"
                 : "=r"(r[0]), "=r"(r[1]), "=r"(r[2]), "=r"(r[3]) : "r"(addr));
}
__device__ __forceinline__ void ldsm_x2(uint32_t* r, uint32_t addr) {
    asm volatile("ldmatrix.sync.aligned.m8n8.x2.shared.b16 {%0,%1}, [%2];"
                 : "=r"(r[0]), "=r"(r[1]) : "r"(addr));
}
__device__ __forceinline__ void mma16816(float* c, const uint32_t* a, const uint32_t* b) {
    asm volatile(
        "mma.sync.aligned.m16n8k16.row.col.f32.f16.f16.f32 "
        "{%0,%1,%2,%3}, {%4,%5,%6,%7}, {%8,%9}, {%0,%1,%2,%3};"
        : "+f"(c[0]), "+f"(c[1]), "+f"(c[2]), "+f"(c[3])
        : "r"(a[0]), "r"(a[1]), "r"(a[2]), "r"(a[3]), "r"(b[0]), "r"(b[1]));
}
__device__ __forceinline__ uint32_t pack2(float v0, float v1, uint32_t& lo) {
    __half h0 = __float2half_rn(v0), h1 = __float2half_rn(v1);
    __half l0 = __float2half_rn(v0 - __half2float(h0));
    __half l1 = __float2half_rn(v1 - __half2float(h1));
    lo = (uint32_t)__half_as_ushort(l0) | ((uint32_t)__half_as_ushort(l1) << 16);
    return (uint32_t)__half_as_ushort(h0) | ((uint32_t)__half_as_ushort(h1) << 16);
}

// ---------------------------------------------------------------------------
// Prep kernels
// ---------------------------------------------------------------------------
__global__ void prep_win(const float* __restrict__ v, const float* __restrict__ g) {
    const int o = blockIdx.x;
    __shared__ float red[256];
    float s = 0.f;
    for (int i = threadIdx.x; i < CEMB; i += 256) {
        float a = v[o * CEMB + i];
        s += a * a;
    }
    red[threadIdx.x] = s;
    __syncthreads();
    for (int st = 128; st > 0; st >>= 1) {
        if (threadIdx.x < st) red[threadIdx.x] += red[threadIdx.x + st];
        __syncthreads();
    }
    const float scale = g[o] / sqrtf(red[0]);
    for (int i = threadIdx.x; i < CEMB; i += 256) {
        float w = v[o * CEMB + i] * scale;
        __half h = __float2half_rn(w);
        g_Winh[o * CEMB + i] = h;
        g_Winl[o * CEMB + i] = __float2half_rn(w - __half2float(h));
    }
}

__global__ void prep_wout(const float* __restrict__ v, const float* __restrict__ g) {
    const int o = blockIdx.x;
    const int t = threadIdx.x;
    const float a = v[o * CCB + t];
    __shared__ float red[64];
    red[t] = a * a;
    __syncthreads();
    for (int st = 32; st > 0; st >>= 1) {
        if (t < st) red[t] += red[t + st];
        __syncthreads();
    }
    g_Wout[o * CCB + t] = a * (g[o] / sqrtf(red[0]));
}

// cb_n = cb / max(||cb||,1e-12); fp16 split [ch|cl]; c_half = 0.5*||cb_n||^2
__global__ void prep_cb(const float* __restrict__ cb, float* __restrict__ out) {
    const int k = blockIdx.x;
    const int t = threadIdx.x;
    const float a = cb[k * CCB + t];
    __shared__ float red[64];
    red[t] = a * a;
    __syncthreads();
    for (int st = 32; st > 0; st >>= 1) {
        if (t < st) red[t] += red[t + st];
        __syncthreads();
    }
    const float denom = fmaxf(sqrtf(red[0]), 1e-12f);
    const float e = a / denom;
    __half h = __float2half_rn(e);
    g_cbs[k * 128 + t]      = h;
    g_cbs[k * 128 + 64 + t] = __float2half_rn(e - __half2float(h));
    __syncthreads();
    red[t] = e * e;
    __syncthreads();
    for (int st = 32; st > 0; st >>= 1) {
        if (t < st) red[t] += red[t + st];
        __syncthreads();
    }
    if (t == 0) g_chalf[k] = 0.5f * red[0];
    if (k == 0 && t == 0) {
        out[OUT_CBLOSS] = 0.f;
        out[OUT_COMMIT] = 0.f;
    }
}

// ---------------------------------------------------------------------------
// x_proj via mma.sync, 3-term fp16 split.
// D[o,t] = sum_i W[o,i] x[i,t]; A = W (row-major [o][k]), B = x ([k][t], via
// ldmatrix.trans). CTA: 128 tokens x all 64 o; 4 warps, warp w = o-rows w*16..+15.
// K loop: 16 chunks of 64; x floats cp.async-staged + converted in-kernel.
// ---------------------------------------------------------------------------
#define XKC       64
#define XNCHUNK   (CEMB / XKC)            // 16
#define XS_STG0   0                        // 32 KB float stage (64 x 128 f32)
#define XS_STG1   32768
#define XS_A0     65536                    // [Ah 8KB | Al 8KB]
#define XS_A1     81920
#define XS_BH     98304                    // 16 KB (64 x 128 halves, swizzled)
#define XS_BL     114688                   // 16 KB
#define XS_TOTAL  131072
#define XS_STG(p) ((p) ? XS_STG1 : XS_STG0)
#define XS_A(p)   ((p) ? XS_A1 : XS_A0)

__global__ __launch_bounds__(128, 1) void xproj_mma(const float* __restrict__ x,
                                                    float* __restrict__ out) {
    extern __shared__ __align__(256) char smem[];
    const uint32_t smb = smem_u32(smem);
    const int tid  = threadIdx.x;
    const int wid  = tid >> 5;
    const int lane = tid & 31;

    const int b  = blockIdx.y;
    const int t0 = blockIdx.x * 128;

    // ---- prefetch chunk 0 (A halves + x floats) ----
    {
        const char* wh = (const char*)g_Winh;
        const char* wl = (const char*)g_Winl;
#pragma unroll
        for (int j = 0; j < 8; j++) {                 // A: 1024 x 16B
            int idx = tid + j * 128;
            int s = idx >> 9, rem = idx & 511;
            int o = rem >> 3, u = rem & 7;
            const char* src = (s ? wl : wh) + o * 2048 + u * 16;
            cpasync16(smb + XS_A0 + s * 8192 + o * 128 + ((u ^ (o & 7)) * 16), src);
        }
#pragma unroll
        for (int j = 0; j < 16; j++) {                // X: 2048 x 16B
            int idx = tid + j * 128;
            int i = idx >> 5, u = idx & 31;
            cpasync16(smb + XS_STG0 + i * 512 + u * 16,
                      (const char*)x + (((size_t)b * CEMB + i) * TT + t0) * 4 + u * 16);
        }
        CP_COMMIT();
    }

    float acc[16][4];
#pragma unroll
    for (int i = 0; i < 16; i++)
#pragma unroll
        for (int j = 0; j < 4; j++) acc[i][j] = 0.f;

    const uint32_t r7 = lane & 7;

    for (int c = 0; c < XNCHUNK; c++) {
        const int p = c & 1;
        if (c < XNCHUNK - 1) {
            const int pn = p ^ 1;
            const int cn = c + 1;
            const char* wh = (const char*)g_Winh;
            const char* wl = (const char*)g_Winl;
#pragma unroll
            for (int j = 0; j < 8; j++) {
                int idx = tid + j * 128;
                int s = idx >> 9, rem = idx & 511;
                int o = rem >> 3, u = rem & 7;
                const char* src = (s ? wl : wh) + o * 2048 + cn * 128 + u * 16;
                cpasync16(smb + XS_A(pn) + s * 8192 + o * 128 + ((u ^ (o & 7)) * 16), src);
            }
#pragma unroll
            for (int j = 0; j < 16; j++) {
                int idx = tid + j * 128;
                int i = idx >> 5, u = idx & 31;
                cpasync16(smb + XS_STG(pn) + i * 512 + u * 16,
                          (const char*)x + (((size_t)b * CEMB + cn * XKC + i) * TT + t0) * 4 + u * 16);
            }
            CP_COMMIT();
            CP_WAIT(1);
        } else {
            CP_WAIT(0);
        }
        __syncthreads();   // stage/A ready; prev-chunk mma done (B safe to overwrite)

        // ---- convert x floats -> Bh/Bl halves (swizzled [i][t]) ----
#pragma unroll
        for (int j = 0; j < 16; j++) {
            int idx = tid + j * 128;
            int i = idx >> 5, q = idx & 31;          // q = float4 index in row
            float4 f = *(const float4*)(smem + XS_STG(p) + i * 512 + q * 16);
            uint32_t lo0, lo1;
            uint32_t h0 = pack2(f.x, f.y, lo0);
            uint32_t h1 = pack2(f.z, f.w, lo1);
            uint32_t off = i * 256 + (((q >> 1) ^ (i & 7)) * 16) + (q & 1) * 8;
            *(uint2*)(smem + XS_BH + off) = make_uint2(h0, h1);
            *(uint2*)(smem + XS_BL + off) = make_uint2(lo0, lo1);
        }
        __syncthreads();

        // ---- A fragments for this chunk (warp's 16 o-rows) ----
        uint32_t ah[4][4], al[4][4];
        {
            const uint32_t rowb = smb + XS_A(p) + (uint32_t)(wid * 16 + (lane & 15)) * 128;
            const uint32_t a4 = (lane >> 4);
#pragma unroll
            for (int kt = 0; kt < 4; kt++) {
                ldsm_x4(ah[kt], rowb + (((2 * kt + a4) ^ r7) * 16));
                ldsm_x4(al[kt], rowb + 8192 + (((2 * kt + a4) ^ r7) * 16));
            }
        }

        // ---- B fragments + MMA, per n-pair (2 n-tiles of 8 tokens) ----
        const uint32_t g = lane >> 3;                 // matrix group 0..3
        const uint32_t rr = lane & 7;
#pragma unroll
        for (int np = 0; np < 8; np++) {
            uint32_t bh[4][4], bl[4][4];
#pragma unroll
            for (int kt = 0; kt < 4; kt++) {
                uint32_t k = kt * 16 + (g & 1) * 8 + rr;
                uint32_t unit = (uint32_t)(2 * np) + (g >> 1);
                uint32_t boff = k * 256 + ((unit ^ (k & 7)) * 16);
                ldsm_x4_t(bh[kt], smb + XS_BH + boff);
                ldsm_x4_t(bl[kt], smb + XS_BL + boff);
            }
#pragma unroll
            for (int kt = 0; kt < 4; kt++) {
                mma16816(acc[2 * np],     ah[kt], bh[kt]);
                mma16816(acc[2 * np + 1], ah[kt], bh[kt] + 2);
                mma16816(acc[2 * np],     al[kt], bh[kt]);
                mma16816(acc[2 * np + 1], al[kt], bh[kt] + 2);
                mma16816(acc[2 * np],     ah[kt], bl[kt]);
                mma16816(acc[2 * np + 1], ah[kt], bl[kt] + 2);
            }
        }
        __syncthreads();   // mma done before next convert overwrites B
    }

    // ---- epilogue: store x_proj (float2; region is 8B-aligned only) ----
    const int r0 = lane >> 2;
    const int n0 = 2 * (lane & 3);
    const size_t obase = OUT_XPROJ + ((size_t)b * CCB + wid * 16) * TT + t0;
#pragma unroll
    for (int nt = 0; nt < 16; nt++) {
        size_t col = (size_t)nt * 8 + n0;
        *(float2*)&out[obase + (size_t)r0 * TT + col]       = make_float2(acc[nt][0], acc[nt][1]);
        *(float2*)&out[obase + (size_t)(r0 + 8) * TT + col] = make_float2(acc[nt][2], acc[nt][3]);
    }
}

// ---------------------------------------------------------------------------
// Tensor-core argmin via mma.sync (m16n8k16 fp16 -> fp32), 3-term split.
// Per CTA: 128 tokens vs 4096 codes. 4 warps, warp w owns tokens w*32..+31.
// score = dot(xp, cb_n)*inv - 0.5||cb_n||^2 ; running argmax == ref argmin.
// ---------------------------------------------------------------------------
#define NCH       128                          // codes per chunk
#define NCHUNKS   (KK / NCH)                   // 32
#define SM_INV    0                            // 512 B  (float inv[128])
#define SM_BESTK  512                          // 512 B  (int bestk[128])
#define SM_CHALF  1024                         // 16 KB  (float chalf[4096])
#define SM_A      17408                        // 32 KB  (128 tokens x 256B [xh|xl])
#define SM_B0     50176                        // 32 KB
#define SM_B1     82944                        // 32 KB
#define SM_TOTAL  115712
#define SM_B(p)   ((p) ? SM_B1 : SM_B0)

__global__ __launch_bounds__(128, 1) void argmin_mma(float* __restrict__ out,
                                                     const float* __restrict__ cb_raw) {
    extern __shared__ __align__(256) char smem[];
    const uint32_t smb = smem_u32(smem);
    const int tid  = threadIdx.x;
    const int wid  = tid >> 5;
    const int lane = tid & 31;
    const int g7   = lane >> 2;     // C-fragment row group
    const int tg   = lane & 3;      // C-fragment col group

    const int token = blockIdx.x * 128 + tid;
    const int b = token >> 11;
    const int t = token & (TT - 1);

    // ---- kick off chalf + chunk0 prefetch (group 0) ----
    {
#pragma unroll
        for (int i = tid; i < 1024; i += 128)                       // 16 KB chalf
            cpasync16(smb + SM_CHALF + i * 16, (const char*)g_chalf + i * 16);
#pragma unroll
        for (int i = tid; i < 2048; i += 128) {                     // 32 KB chunk0
            int r = i >> 4, s = i & 15;
            cpasync16(smb + SM_B0 + r * 256 + ((s ^ (r & 7)) * 16),
                      (const char*)g_cbs + i * 16);
        }
        CP_COMMIT();
    }

    // ---- load x_proj column, inv, build swizzled A panel [xh|xl] ----
    {
        float xp[64];
        const size_t xbase = OUT_XPROJ + (size_t)b * CCB * TT + t;
#pragma unroll
        for (int c = 0; c < 64; c++) xp[c] = out[xbase + (size_t)c * TT];
        float ss = 0.f;
#pragma unroll
        for (int c = 0; c < 64; c++) ss = fmaf(xp[c], xp[c], ss);
        ((float*)(smem + SM_INV))[tid] = 1.0f / fmaxf(sqrtf(ss), 1e-12f);

#pragma unroll
        for (int s = 0; s < 8; s++) {
            uint32_t hw[4], lw[4];
#pragma unroll
            for (int j = 0; j < 4; j++)
                hw[j] = pack2(xp[8 * s + 2 * j], xp[8 * s + 2 * j + 1], lw[j]);
            uint32_t off = (uint32_t)tid * 256 + ((s ^ (tid & 7)) * 16);
            *(uint4*)(smem + SM_A + off)       = make_uint4(hw[0], hw[1], hw[2], hw[3]);
            *(uint4*)(smem + SM_A + off + 128) = make_uint4(lw[0], lw[1], lw[2], lw[3]);
        }
    }
    __syncthreads();

    // ---- load resident A fragments (2 m-tiles x 4 k-tiles, hi & lo) ----
    uint32_t ah[2][4][4], al[2][4][4];
#pragma unroll
    for (int mt = 0; mt < 2; mt++) {
        const uint32_t rowb = smb + SM_A + (uint32_t)(wid * 32 + mt * 16 + (lane & 15)) * 256;
        const uint32_t r7 = (lane & 7);
        const uint32_t a4 = (lane >> 4);
#pragma unroll
        for (int kt = 0; kt < 4; kt++) {
            ldsm_x4(ah[mt][kt], rowb + (((2 * kt + a4) ^ r7) * 16));
            ldsm_x4(al[mt][kt], rowb + (((8 + 2 * kt + a4) ^ r7) * 16));
        }
    }

    // per-lane B ldmatrix offsets (8 k-tiles: ch0-3, cl0-3)
    uint32_t obch[4], obcl[4];
    {
        const uint32_t r7 = (lane & 7);
        const uint32_t a2 = (lane >> 3) & 1;
#pragma unroll
        for (int kt = 0; kt < 4; kt++) {
            obch[kt] = r7 * 256 + (((2 * kt + a2) ^ r7) * 16);
            obcl[kt] = r7 * 256 + (((8 + 2 * kt + a2) ^ r7) * 16);
        }
    }

    // per-lane token inverses
    float invr[4];
    {
        const float* si = (const float*)(smem + SM_INV);
#pragma unroll
        for (int r = 0; r < 4; r++) invr[r] = si[wid * 32 + r * 8 + g7];
    }

    float bestv[4] = {-1e30f, -1e30f, -1e30f, -1e30f};
    int   bestk[4] = {0, 0, 0, 0};
    const float* chs = (const float*)(smem + SM_CHALF);

    for (int c = 0; c < NCHUNKS; c++) {
        const int p = c & 1;
        if (c < NCHUNKS - 1) {
            const int pn = (c + 1) & 1;
            const char* src = (const char*)g_cbs + (size_t)(c + 1) * NCH * 256;
#pragma unroll
            for (int i = tid; i < 2048; i += 128) {
                int r = i >> 4, s = i & 15;
                cpasync16(smb + SM_B(pn) + r * 256 + ((s ^ (r & 7)) * 16), src + i * 16);
            }
            CP_COMMIT();
            CP_WAIT(1);
        } else {
            CP_WAIT(0);
        }
        __syncthreads();

        const uint32_t bbase = smb + SM_B(p);
        const int kchunk = c * NCH;

#pragma unroll 2
        for (int nt = 0; nt < NCH / 8; nt++) {
            const uint32_t nb = bbase + (uint32_t)nt * 8 * 256;
            uint32_t bch[4][2], bcl[4][2];
#pragma unroll
            for (int kt = 0; kt < 4; kt++) ldsm_x2(bch[kt], nb + obch[kt]);
#pragma unroll
            for (int kt = 0; kt < 4; kt++) ldsm_x2(bcl[kt], nb + obcl[kt]);

            float acc[8];
#pragma unroll
            for (int i = 0; i < 8; i++) acc[i] = 0.f;
#pragma unroll
            for (int mt = 0; mt < 2; mt++) {
#pragma unroll
                for (int kt = 0; kt < 4; kt++) mma16816(acc + 4 * mt, ah[mt][kt], bch[kt]);
#pragma unroll
                for (int kt = 0; kt < 4; kt++) mma16816(acc + 4 * mt, al[mt][kt], bch[kt]);
#pragma unroll
                for (int kt = 0; kt < 4; kt++) mma16816(acc + 4 * mt, ah[mt][kt], bcl[kt]);
            }

            const int col0 = kchunk + nt * 8 + 2 * tg;
            const float2 chv = *(const float2*)&chs[kchunk + nt * 8 + 2 * tg];
            float s;
            s = fmaf(acc[0], invr[0], -chv.x); if (s > bestv[0]) { bestv[0] = s; bestk[0] = col0; }
            s = fmaf(acc[1], invr[0], -chv.y); if (s > bestv[0]) { bestv[0] = s; bestk[0] = col0 + 1; }
            s = fmaf(acc[2], invr[1], -chv.x); if (s > bestv[1]) { bestv[1] = s; bestk[1] = col0; }
            s = fmaf(acc[3], invr[1], -chv.y); if (s > bestv[1]) { bestv[1] = s; bestk[1] = col0 + 1; }
            s = fmaf(acc[4], invr[2], -chv.x); if (s > bestv[2]) { bestv[2] = s; bestk[2] = col0; }
            s = fmaf(acc[5], invr[2], -chv.y); if (s > bestv[2]) { bestv[2] = s; bestk[2] = col0 + 1; }
            s = fmaf(acc[6], invr[3], -chv.x); if (s > bestv[3]) { bestv[3] = s; bestk[3] = col0; }
            s = fmaf(acc[7], invr[3], -chv.y); if (s > bestv[3]) { bestv[3] = s; bestk[3] = col0 + 1; }
        }
        __syncthreads();
    }

    // ---- combine across the 4 lanes of each quad (tie -> smaller k) ----
#pragma unroll
    for (int r = 0; r < 4; r++) {
#pragma unroll
        for (int off = 1; off < 4; off <<= 1) {
            float ov = __shfl_xor_sync(0xffffffffu, bestv[r], off);
            int   ok = __shfl_xor_sync(0xffffffffu, bestk[r], off);
            if (ov > bestv[r] || (ov == bestv[r] && ok < bestk[r])) {
                bestv[r] = ov; bestk[r] = ok;
            }
        }
    }
    if (tg == 0) {
        int* sbk = (int*)(smem + SM_BESTK);
#pragma unroll
        for (int r = 0; r < 4; r++) sbk[wid * 32 + r * 8 + g7] = bestk[r];
    }
    __syncthreads();

    // ---- tail: codes, gather q_proj, losses ----
    const int bk = ((const int*)(smem + SM_BESTK))[tid];
    out[OUT_CODES + token] = (float)bk;

    float xp[64];
    const size_t xbase = OUT_XPROJ + (size_t)b * CCB * TT + t;
#pragma unroll
    for (int c = 0; c < 64; c++) xp[c] = out[xbase + (size_t)c * TT];

    float ls = 0.f;
    const float* q = cb_raw + (size_t)bk * CCB;
    const size_t qbase = OUT_QPROJ + (size_t)b * CCB * TT + t;
#pragma unroll
    for (int c = 0; c < 64; c++) {
        float qv = q[c];
        out[qbase + (size_t)c * TT] = qv;
        float dd = xp[c] - qv;
        ls = fmaf(dd, dd, ls);
    }

    float* red = (float*)(smem + SM_INV);     // inv no longer needed
    red[tid] = ls;
    __syncthreads();
    for (int st = 64; st > 0; st >>= 1) {
        if (tid < st) red[tid] += red[tid + st];
        __syncthreads();
    }
    if (tid == 0) {
        float v = red[0] * LOSS_INV;
        atomicAdd(&out[OUT_CBLOSS], v);
        atomicAdd(&out[OUT_COMMIT], v);
    }
}

// ---------------------------------------------------------------------------
// W_out GEMM (fp32 scalar — unchanged this round)
// ---------------------------------------------------------------------------
__global__ __launch_bounds__(256) void wout_kernel(float* __restrict__ out) {
    const int b  = blockIdx.z;
    const int o0 = blockIdx.y * 64;
    const int t0 = blockIdx.x * 64;
    __shared__ float sW[64][68];
    __shared__ float sQ[64][68];
    const int tid = threadIdx.x;
    const int tx = tid & 15;
    const int ty = tid >> 4;

#pragma unroll
    for (int j = 0; j < 16; j++) {
        int idx = tid + j * 256;
        int c = idx & 63, o = idx >> 6;
        sW[c][o] = g_Wout[(size_t)(o0 + o) * CCB + c];
    }
#pragma unroll
    for (int j = 0; j < 4; j++) {
        int v = tid + j * 256;
        int c = v >> 4, t4 = (v & 15) << 2;
        size_t src = OUT_QPROJ + ((size_t)b * CCB + c) * TT + t0 + t4;
        float2 a0 = *(const float2*)&out[src];
        float2 a1 = *(const float2*)&out[src + 2];
        sQ[c][t4 + 0] = a0.x; sQ[c][t4 + 1] = a0.y;
        sQ[c][t4 + 2] = a1.x; sQ[c][t4 + 3] = a1.y;
    }
    __syncthreads();

    float acc[4][4];
#pragma unroll
    for (int i = 0; i < 4; i++)
#pragma unroll
        for (int j = 0; j < 4; j++) acc[i][j] = 0.f;

#pragma unroll
    for (int c = 0; c < 64; c++) {
        float4 wf = *(const float4*)&sW[c][ty * 4];
        float4 qf = *(const float4*)&sQ[c][tx * 4];
        float w[4] = {wf.x, wf.y, wf.z, wf.w};
        float qv[4] = {qf.x, qf.y, qf.z, qf.w};
#pragma unroll
        for (int oo = 0; oo < 4; oo++)
#pragma unroll
            for (int tt = 0; tt < 4; tt++)
                acc[oo][tt] = fmaf(w[oo], qv[tt], acc[oo][tt]);
    }
#pragma unroll
    for (int oo = 0; oo < 4; oo++) {
        size_t base = OUT_QUANT + ((size_t)b * CEMB + o0 + ty * 4 + oo) * TT + t0 + tx * 4;
        *(float4*)&out[base] = make_float4(acc[oo][0], acc[oo][1], acc[oo][2], acc[oo][3]);
    }
}

// ---------------------------------------------------------------------------
extern "C" void kernel_launch(void* const* d_in, const int* in_sizes, int n_in,
                              void* d_out, int out_size) {
    const float* x     = (const float*)d_in[0];
    const float* v_in  = (const float*)d_in[1];
    const float* g_in  = (const float*)d_in[2];
    const float* v_out = (const float*)d_in[3];
    const float* g_out = (const float*)d_in[4];
    const float* cb    = (const float*)d_in[5];
    float* out = (float*)d_out;

    cudaFuncSetAttribute(xproj_mma, cudaFuncAttributeMaxDynamicSharedMemorySize, XS_TOTAL);
    cudaFuncSetAttribute(argmin_mma, cudaFuncAttributeMaxDynamicSharedMemorySize, SM_TOTAL);

    prep_win<<<CCB, 256>>>(v_in, g_in);
    prep_wout<<<CEMB, 64>>>(v_out, g_out);
    prep_cb<<<KK, 64>>>(cb, out);
    xproj_mma<<<dim3(TT / 128, BB), 128, XS_TOTAL>>>(x, out);
    argmin_mma<<<BB * TT / 128, 128, SM_TOTAL>>>(out, cb);
    wout_kernel<<<dim3(TT / 64, CEMB / 64, BB), 256>>>(out);
}